// round 4
// baseline (speedup 1.0000x reference)
#include <cuda_runtime.h>
#include <math.h>

// Tropical (max-plus) depthwise 5x5 conv, stride 1, pad 2 (-inf), dilation 1.
// x: [8,32,224,224] f32, kernel: [32,1,5,5] f32, out: [8,32,224,224] f32.
// out[b,c,h,w] = max_{i,j in 0..4} ( x_pad[b,c,h+i,w+j] + kflip[c,i,j] )
// where kflip[c,i,j] = kernel[c,0,4-i,4-j].
//
// Each thread computes a 4-wide x 8-tall output block:
//   - 12 input rows, each loaded as 3 aligned float4 (12 floats, need cols
//     [4*tx-2 .. 4*tx+5], covered by aligned segments 4*tx-4, 4*tx, 4*tx+4)
//   - full register reuse vertically (each row feeds up to 5 output rows)
// Plane layout: 256 planes (b*c), 28 row-groups of 8, 56 col-groups of 4.
// 1568 threads per plane = exactly 49 warps -> plane and weights are
// warp-uniform (broadcast weight loads).

#define HW 224
#define NEG_INF (-INFINITY)

__global__ __launch_bounds__(256) void tropical_conv_kernel(
    const float* __restrict__ x,
    const float* __restrict__ w,
    float* __restrict__ out)
{
    const int gid   = blockIdx.x * blockDim.x + threadIdx.x;
    const int plane = gid / 1568;           // b*32 + c, 0..255
    const int rem   = gid - plane * 1568;
    const int rg    = rem / 56;             // row group, 0..27 (rows rg*8 .. rg*8+7)
    const int tx    = rem - rg * 56;        // col group, 0..55 (cols tx*4 .. tx*4+3)
    const int c     = plane & 31;

    // Flipped weights (warp-uniform -> broadcast loads)
    float wf[25];
#pragma unroll
    for (int i = 0; i < 5; i++)
#pragma unroll
        for (int j = 0; j < 5; j++)
            wf[i * 5 + j] = __ldg(&w[c * 25 + (4 - i) * 5 + (4 - j)]);

    float acc[8][4];
#pragma unroll
    for (int oh = 0; oh < 8; oh++)
#pragma unroll
        for (int q = 0; q < 4; q++)
            acc[oh][q] = NEG_INF;

    const float* xp = x + (size_t)plane * (HW * HW);
    const int col0  = tx * 4 - 4;           // first col of the 12-float window
    const int row0  = rg * 8 - 2;           // first input row of the 12-row window

#pragma unroll
    for (int r = 0; r < 12; r++) {
        const int gr = row0 + r;
        float v[12];
        if (gr >= 0 && gr < HW) {
            const float* rowp = xp + gr * HW;
#pragma unroll
            for (int s = 0; s < 3; s++) {
                const int cc = col0 + 4 * s;
                if (cc >= 0 && cc <= HW - 4) {
                    const float4 t = *reinterpret_cast<const float4*>(rowp + cc);
                    v[4 * s + 0] = t.x;
                    v[4 * s + 1] = t.y;
                    v[4 * s + 2] = t.z;
                    v[4 * s + 3] = t.w;
                } else {
                    v[4 * s + 0] = NEG_INF;
                    v[4 * s + 1] = NEG_INF;
                    v[4 * s + 2] = NEG_INF;
                    v[4 * s + 3] = NEG_INF;
                }
            }
        } else {
#pragma unroll
            for (int q = 0; q < 12; q++) v[q] = NEG_INF;
        }

        // This input row r feeds output rows oh = r - i for i in 0..4
#pragma unroll
        for (int i = 0; i < 5; i++) {
            const int oh = r - i;
            if (oh >= 0 && oh < 8) {        // compile-time after full unroll
#pragma unroll
                for (int j = 0; j < 5; j++) {
                    const float wv = wf[i * 5 + j];
#pragma unroll
                    for (int q = 0; q < 4; q++)
                        acc[oh][q] = fmaxf(acc[oh][q], v[2 + j + q] + wv);
                }
            }
        }
    }

    float* op = out + (size_t)plane * (HW * HW) + (rg * 8) * HW + tx * 4;
#pragma unroll
    for (int oh = 0; oh < 8; oh++) {
        float4 t;
        t.x = acc[oh][0];
        t.y = acc[oh][1];
        t.z = acc[oh][2];
        t.w = acc[oh][3];
        *reinterpret_cast<float4*>(op + oh * HW) = t;
    }
}

extern "C" void kernel_launch(void* const* d_in, const int* in_sizes, int n_in,
                              void* d_out, int out_size)
{
    const float* x = (const float*)d_in[0];
    const float* w = (const float*)d_in[1];
    float* out     = (float*)d_out;
    // 256 planes * 28 row-groups * 56 col-groups = 401408 threads = 1568 blocks
    tropical_conv_kernel<<<1568, 256>>>(x, w, out);
}

// round 5
// speedup vs baseline: 1.1756x; 1.1756x over previous
#include <cuda_runtime.h>
#include <math.h>

// Tropical (max-plus) depthwise 5x5 conv, stride 1, pad 2 (-inf), dilation 1.
// x: [8,32,224,224] f32, kernel: [32,1,5,5] f32, out same shape as x.
// out[b,c,h,w] = max_{i,j} ( x_pad[b,c,h+i,w+j] + kflip[c,i,j] ),
// kflip[c,i,j] = kernel[c,0,4-i,4-j].
//
// R4 design: streaming 8-tall x 4-wide tile per thread.
//  - Output cols [4tx-2, 4tx+1]: needed input cols [4tx-4, 4tx+3] are exactly
//    TWO aligned float4 loads per input row (was three).
//  - Cyclic 5-row accumulator window (20 regs instead of 32): output row oh
//    accumulates only during input rows r = oh..oh+4; stored when complete.
//  - __launch_bounds__(256,4) pins regs <= 64 -> 4 CTAs/SM (50% occ target).
// Plane layout: 57 col-groups x 28 row-groups = 1596 threads/plane,
// 256 planes -> 1596 blocks of 256.

#define HW 224
#define NEG_INF (-INFINITY)

__global__ __launch_bounds__(256, 4) void tropical_conv_kernel(
    const float* __restrict__ x,
    const float* __restrict__ w,
    float* __restrict__ out)
{
    const int gid   = blockIdx.x * blockDim.x + threadIdx.x;
    const int plane = gid / 1596;           // b*32 + c, 0..255
    const int rem   = gid - plane * 1596;
    const int rg    = rem / 57;             // row group 0..27 (output rows rg*8..rg*8+7)
    const int tx    = rem - rg * 57;        // col group 0..56
    const int c     = plane & 31;

    // Flipped weights
    float wf[25];
#pragma unroll
    for (int i = 0; i < 5; i++)
#pragma unroll
        for (int j = 0; j < 5; j++)
            wf[i * 5 + j] = __ldg(&w[c * 25 + (4 - i) * 5 + (4 - j)]);

    const float* xp = x + (size_t)plane * (HW * HW);
    float* op_base  = out + (size_t)plane * (HW * HW) + (rg * 8) * HW + (tx * 4 - 2);

    const int colL = tx * 4 - 4;            // first (left) aligned quad: cols colL..colL+3
    const int row0 = rg * 8 - 2;            // first input row of the 12-row window

    const bool ldL = (tx > 0);              // left quad in-bounds  (colL >= 0)
    const bool ldR = (tx < 56);             // right quad in-bounds (colL+4 <= 220)
    const bool stL = (tx > 0);              // store cols 4tx-2,4tx-1 valid
    const bool stR = (tx < 56);             // store cols 4tx,  4tx+1 valid

    float acc[5][4];                        // cyclic window of 5 active output rows

#pragma unroll
    for (int r = 0; r < 12; r++) {
        const int gr = row0 + r;
        const bool rowok = (gr >= 0) && (gr < HW);

        float v[8];                         // input cols colL .. colL+7
        if (rowok) {
            const float* rowp = xp + gr * HW + colL;
            if (ldL) {
                const float4 t = *reinterpret_cast<const float4*>(rowp);
                v[0] = t.x; v[1] = t.y; v[2] = t.z; v[3] = t.w;
            } else {
                v[0] = NEG_INF; v[1] = NEG_INF; v[2] = NEG_INF; v[3] = NEG_INF;
            }
            if (ldR) {
                const float4 t = *reinterpret_cast<const float4*>(rowp + 4);
                v[4] = t.x; v[5] = t.y; v[6] = t.z; v[7] = t.w;
            } else {
                v[4] = NEG_INF; v[5] = NEG_INF; v[6] = NEG_INF; v[7] = NEG_INF;
            }
        } else {
#pragma unroll
            for (int q = 0; q < 8; q++) v[q] = NEG_INF;
        }

        // Output row oh = r begins accumulating at this input row.
        if (r < 8) {
            const int s = r % 5;
#pragma unroll
            for (int q = 0; q < 4; q++) acc[s][q] = NEG_INF;
        }

        // Input row r contributes to output rows oh = r - i, i = 0..4.
#pragma unroll
        for (int i = 0; i < 5; i++) {
            const int oh = r - i;
            if (oh >= 0 && oh < 8) {        // compile-time after unroll
                const int s = oh % 5;
#pragma unroll
                for (int j = 0; j < 5; j++) {
                    const float wv = wf[i * 5 + j];
#pragma unroll
                    for (int q = 0; q < 4; q++)
                        acc[s][q] = fmaxf(acc[s][q], v[q + j] + wv);
                }
            }
        }

        // Output row oh = r - 4 is complete after this input row: store it.
        if (r >= 4) {
            const int oh = r - 4;
            const int s  = oh % 5;
            float* orow  = op_base + oh * HW;
            if (stL) {
                float2 t; t.x = acc[s][0]; t.y = acc[s][1];
                *reinterpret_cast<float2*>(orow) = t;
            }
            if (stR) {
                float2 t; t.x = acc[s][2]; t.y = acc[s][3];
                *reinterpret_cast<float2*>(orow + 2) = t;
            }
        }
    }
}

extern "C" void kernel_launch(void* const* d_in, const int* in_sizes, int n_in,
                              void* d_out, int out_size)
{
    const float* x = (const float*)d_in[0];
    const float* w = (const float*)d_in[1];
    float* out     = (float*)d_out;
    // 256 planes * 28 row-groups * 57 col-groups = 408576 threads = 1596 blocks
    tropical_conv_kernel<<<1596, 256>>>(x, w, out);
}